// round 15
// baseline (speedup 1.0000x reference)
#include <cuda_runtime.h>

#define IMD 224
#define HWPX (IMD * IMD)
#define TILES_X 7
#define TILES_PER_IM (TILES_X * TILES_X)   // 49
#define NTILES (TILES_PER_IM * 64)          // 3136
#define NCTAS 740                           // 148 SMs x 5 resident CTAs

// Persistent-CTA version: one resident wave (740 CTAs), each loops over
// 32x32 tiles. Per tile:
//  Phase 1: float4 coalesced loads of C0,C1,M1,M2 into padded smem.
//  Phase 2: x-fast lanes, 24-gather burst per pixel, owner-private writeback.
//  Phase 3: float4 coalesced stores.
__global__ __launch_bounds__(256, 5) void vm_kernel(
    const float* __restrict__ im1, const float* __restrict__ im2,
    const float* __restrict__ C,   const float* __restrict__ M1,
    const float* __restrict__ M2,  float* __restrict__ out)
{
    __shared__ float sA[32][33];  // C0  -> out c0
    __shared__ float sB[32][33];  // C1  -> out c1
    __shared__ float sD[32][33];  // M1  -> out c2
    __shared__ float sE[32][33];  // M2

    const int tid = threadIdx.x;
    const int dx = tid & 31;        // lane -> x (gathers coalesced)
    const int wp = tid >> 5;        // warp 0..7
    const int pdx = tid >> 3;       // phase1/3 row
    const int pdy = (tid & 7) * 4;  // phase1/3 col (float4)

    for (int t = blockIdx.x; t < NTILES; t += NCTAS) {
        const int n  = t / TILES_PER_IM;
        const int r  = t - n * TILES_PER_IM;
        const int ty = r / TILES_X;
        const int tx = r - ty * TILES_X;
        const int x0 = ty * 32;
        const int y0 = tx * 32;

        const float* __restrict__ Cb0 = C  + (size_t)n * 2 * HWPX;
        const float* __restrict__ Cb1 = Cb0 + HWPX;
        const float* __restrict__ M1b = M1 + (size_t)n * HWPX;
        const float* __restrict__ M2b = M2 + (size_t)n * HWPX;
        const float* __restrict__ I1b = im1 + (size_t)n * 3 * HWPX;
        const float* __restrict__ I2b = im2 + (size_t)n * 3 * HWPX;

        __syncthreads();   // smem safe to overwrite (prev tile's phase3 done)

        // ---- Phase 1: vectorized coalesced tile load ----
        {
            const int g = (x0 + pdx) * IMD + (y0 + pdy);   // 16B aligned
            float4 a = *(const float4*)(Cb0 + g);
            float4 b = *(const float4*)(Cb1 + g);
            float4 d = *(const float4*)(M1b + g);
            float4 e = *(const float4*)(M2b + g);
            sA[pdx][pdy] = a.x; sA[pdx][pdy+1] = a.y; sA[pdx][pdy+2] = a.z; sA[pdx][pdy+3] = a.w;
            sB[pdx][pdy] = b.x; sB[pdx][pdy+1] = b.y; sB[pdx][pdy+2] = b.z; sB[pdx][pdy+3] = b.w;
            sD[pdx][pdy] = d.x; sD[pdx][pdy+1] = d.y; sD[pdx][pdy+2] = d.z; sD[pdx][pdy+3] = d.w;
            sE[pdx][pdy] = e.x; sE[pdx][pdy+1] = e.y; sE[pdx][pdy+2] = e.z; sE[pdx][pdy+3] = e.w;
        }
        __syncthreads();

        // ---- Phase 2: x-fast compute, 24-load gather bursts ----
        const float xf = (float)(x0 + dx);

#pragma unroll
        for (int k = 0; k < 4; k++) {
            const int dy = wp + k * 8;
            const float c0 = sA[dx][dy];
            const float c1 = sB[dx][dy];
            const float m1 = sD[dx][dy];
            const float m2 = sE[dx][dy];
            const float yf = (float)(y0 + dy);

            int   idx[2][4];
            float w[2][4];
#pragma unroll
            for (int s = 0; s < 2; s++) {
                const float px = (s == 0) ? (xf + c0) : (xf - c0);
                const float py = (s == 0) ? (yf + c1) : (yf - c1);
                const int ifx = __float2int_rd(px);
                const int ify = __float2int_rd(py);
                const float fx = (float)ifx;
                const float fy = (float)ify;
                const float cxv = ceilf(px);
                const float cyv = ceilf(py);
                const int icx = (int)cxv;
                const int icy = (int)cyv;
                const float wfx = 1.0f - (px - fx);
                const float wcx = 1.0f - (cxv - px);
                const float wfy = 1.0f - (py - fy);
                const float wcy = 1.0f - (cyv - py);
                int i00 = ifx + IMD * ify;
                int i10 = icx + IMD * ify;
                int i01 = ifx + IMD * icy;
                int i11 = icx + IMD * icy;
                idx[s][0] = min(max(i00, 0), HWPX - 1);
                idx[s][1] = min(max(i10, 0), HWPX - 1);
                idx[s][2] = min(max(i01, 0), HWPX - 1);
                idx[s][3] = min(max(i11, 0), HWPX - 1);
                w[s][0] = wfx * wfy;
                w[s][1] = wcx * wfy;
                w[s][2] = wfx * wcy;
                w[s][3] = wcx * wcy;
            }

            float v1[3][4], v2[3][4];
#pragma unroll
            for (int c = 0; c < 3; c++) {
                const float* p1 = I1b + c * HWPX;
                const float* p2 = I2b + c * HWPX;
#pragma unroll
                for (int tt = 0; tt < 4; tt++) {
                    v1[c][tt] = __ldg(p1 + idx[0][tt]);
                    v2[c][tt] = __ldg(p2 + idx[1][tt]);
                }
            }

            float r0, r1, r2;
            {
                float a = ((w[0][0] * v1[0][0] + w[0][1] * v1[0][1])
                         +  w[0][2] * v1[0][2]) + w[0][3] * v1[0][3];
                float b = ((w[1][0] * v2[0][0] + w[1][1] * v2[0][1])
                         +  w[1][2] * v2[0][2]) + w[1][3] * v2[0][3];
                r0 = a * m1 + b * m2;
                a = ((w[0][0] * v1[1][0] + w[0][1] * v1[1][1])
                   +  w[0][2] * v1[1][2]) + w[0][3] * v1[1][3];
                b = ((w[1][0] * v2[1][0] + w[1][1] * v2[1][1])
                   +  w[1][2] * v2[1][2]) + w[1][3] * v2[1][3];
                r1 = a * m1 + b * m2;
                a = ((w[0][0] * v1[2][0] + w[0][1] * v1[2][1])
                   +  w[0][2] * v1[2][2]) + w[0][3] * v1[2][3];
                b = ((w[1][0] * v2[2][0] + w[1][1] * v2[2][1])
                   +  w[1][2] * v2[2][2]) + w[1][3] * v2[2][3];
                r2 = a * m1 + b * m2;
            }

            // Owner-private cells: safe to overwrite without a barrier.
            sA[dx][dy] = r0;
            sB[dx][dy] = r1;
            sD[dx][dy] = r2;
        }
        __syncthreads();

        // ---- Phase 3: vectorized coalesced store ----
        {
            float* __restrict__ ob = out + (size_t)n * 3 * HWPX;
            const int g = (x0 + pdx) * IMD + (y0 + pdy);   // 16B aligned
            float4 v;
            v.x = sA[pdx][pdy]; v.y = sA[pdx][pdy+1]; v.z = sA[pdx][pdy+2]; v.w = sA[pdx][pdy+3];
            *(float4*)(ob + g) = v;
            v.x = sB[pdx][pdy]; v.y = sB[pdx][pdy+1]; v.z = sB[pdx][pdy+2]; v.w = sB[pdx][pdy+3];
            *(float4*)(ob + HWPX + g) = v;
            v.x = sD[pdx][pdy]; v.y = sD[pdx][pdy+1]; v.z = sD[pdx][pdy+2]; v.w = sD[pdx][pdy+3];
            *(float4*)(ob + 2 * HWPX + g) = v;
        }
    }
}

extern "C" void kernel_launch(void* const* d_in, const int* in_sizes, int n_in,
                              void* d_out, int out_size)
{
    const float* im1 = (const float*)d_in[0];
    const float* im2 = (const float*)d_in[1];
    const float* C   = (const float*)d_in[2];
    const float* M1  = (const float*)d_in[3];
    const float* M2  = (const float*)d_in[4];
    float* out = (float*)d_out;

    vm_kernel<<<NCTAS, 256>>>(im1, im2, C, M1, M2, out);
}

// round 17
// speedup vs baseline: 1.4502x; 1.4502x over previous
#include <cuda_runtime.h>

#define IMD 224
#define HWPX (IMD * IMD)

// Tile: 32 x-values (slow dim of p) x 16 y-values (fast dim). Grid (14,7,64).
// Smaller tiles halve the wave-quantization tail (8.48 waves vs 4.24) while
// keeping the warp gather geometry identical (32 x-fast lanes per warp).
// Phase 1: float2 coalesced loads of C0,C1,M1,M2 into padded smem.
// Phase 2: x-fast lanes, 24-gather flat burst per pixel, owner-private writeback.
// Phase 3: float2 coalesced stores.
__global__ __launch_bounds__(256, 5) void vm_kernel(
    const float* __restrict__ im1, const float* __restrict__ im2,
    const float* __restrict__ C,   const float* __restrict__ M1,
    const float* __restrict__ M2,  float* __restrict__ out)
{
    __shared__ float sA[32][17];  // C0  -> out c0
    __shared__ float sB[32][17];  // C1  -> out c1
    __shared__ float sD[32][17];  // M1  -> out c2
    __shared__ float sE[32][17];  // M2

    const int tid = threadIdx.x;
    const int n  = blockIdx.z;
    const int x0 = blockIdx.y * 32;     // 7 x-tiles
    const int y0 = blockIdx.x * 16;     // 14 y-tiles

    const float* __restrict__ Cb0 = C  + (size_t)n * 2 * HWPX;
    const float* __restrict__ Cb1 = Cb0 + HWPX;
    const float* __restrict__ M1b = M1 + (size_t)n * HWPX;
    const float* __restrict__ M2b = M2 + (size_t)n * HWPX;
    const float* __restrict__ I1b = im1 + (size_t)n * 3 * HWPX;
    const float* __restrict__ I2b = im2 + (size_t)n * 3 * HWPX;

    // ---- Phase 1: float2 coalesced tile load ----
    const int pdx = tid >> 3;          // 0..31 (x)
    const int pdy = (tid & 7) * 2;     // 0,2,...,14 (y)
    {
        const int g = (x0 + pdx) * IMD + (y0 + pdy);   // 8B aligned
        float2 a = *(const float2*)(Cb0 + g);
        float2 b = *(const float2*)(Cb1 + g);
        float2 d = *(const float2*)(M1b + g);
        float2 e = *(const float2*)(M2b + g);
        sA[pdx][pdy] = a.x; sA[pdx][pdy+1] = a.y;
        sB[pdx][pdy] = b.x; sB[pdx][pdy+1] = b.y;
        sD[pdx][pdy] = d.x; sD[pdx][pdy+1] = d.y;
        sE[pdx][pdy] = e.x; sE[pdx][pdy+1] = e.y;
    }
    __syncthreads();

    // ---- Phase 2: x-fast compute, flat 24-load gather bursts ----
    const int dx = tid & 31;        // lane -> x (gathers coalesced)
    const int wp = tid >> 5;        // warp 0..7
    const float xf = (float)(x0 + dx);

#pragma unroll
    for (int k = 0; k < 2; k++) {
        const int dy = wp + k * 8;          // 0..15
        const float c0 = sA[dx][dy];
        const float c1 = sB[dx][dy];
        const float m1 = sD[dx][dy];
        const float m2 = sE[dx][dy];
        const float yf = (float)(y0 + dy);

        int   idx[2][4];
        float w[2][4];
#pragma unroll
        for (int s = 0; s < 2; s++) {
            const float px = (s == 0) ? (xf + c0) : (xf - c0);
            const float py = (s == 0) ? (yf + c1) : (yf - c1);
            const int ifx = __float2int_rd(px);
            const int ify = __float2int_rd(py);
            const float fx = (float)ifx;
            const float fy = (float)ify;
            const float cxv = ceilf(px);
            const float cyv = ceilf(py);
            const int icx = (int)cxv;
            const int icy = (int)cyv;
            const float wfx = 1.0f - (px - fx);
            const float wcx = 1.0f - (cxv - px);
            const float wfy = 1.0f - (py - fy);
            const float wcy = 1.0f - (cyv - py);
            int i00 = ifx + IMD * ify;
            int i10 = icx + IMD * ify;
            int i01 = ifx + IMD * icy;
            int i11 = icx + IMD * icy;
            idx[s][0] = min(max(i00, 0), HWPX - 1);
            idx[s][1] = min(max(i10, 0), HWPX - 1);
            idx[s][2] = min(max(i01, 0), HWPX - 1);
            idx[s][3] = min(max(i11, 0), HWPX - 1);
            w[s][0] = wfx * wfy;
            w[s][1] = wcx * wfy;
            w[s][2] = wfx * wcy;
            w[s][3] = wcx * wcy;
        }

        float v1[3][4], v2[3][4];
#pragma unroll
        for (int c = 0; c < 3; c++) {
            const float* p1 = I1b + c * HWPX;
            const float* p2 = I2b + c * HWPX;
#pragma unroll
            for (int t = 0; t < 4; t++) {
                v1[c][t] = __ldg(p1 + idx[0][t]);
                v2[c][t] = __ldg(p2 + idx[1][t]);
            }
        }

#pragma unroll
        for (int c = 0; c < 3; c++) {
            float a = ((w[0][0] * v1[c][0] + w[0][1] * v1[c][1])
                     +  w[0][2] * v1[c][2]) + w[0][3] * v1[c][3];
            float b = ((w[1][0] * v2[c][0] + w[1][1] * v2[c][1])
                     +  w[1][2] * v2[c][2]) + w[1][3] * v2[c][3];
            float r = a * m1 + b * m2;
            // Owner-private cells: safe to overwrite without a barrier.
            if (c == 0) sA[dx][dy] = r;
            else if (c == 1) sB[dx][dy] = r;
            else sD[dx][dy] = r;
        }
    }
    __syncthreads();

    // ---- Phase 3: float2 coalesced store ----
    {
        float* __restrict__ ob = out + (size_t)n * 3 * HWPX;
        const int g = (x0 + pdx) * IMD + (y0 + pdy);   // 8B aligned
        float2 v;
        v.x = sA[pdx][pdy]; v.y = sA[pdx][pdy+1];
        *(float2*)(ob + g) = v;
        v.x = sB[pdx][pdy]; v.y = sB[pdx][pdy+1];
        *(float2*)(ob + HWPX + g) = v;
        v.x = sD[pdx][pdy]; v.y = sD[pdx][pdy+1];
        *(float2*)(ob + 2 * HWPX + g) = v;
    }
}

extern "C" void kernel_launch(void* const* d_in, const int* in_sizes, int n_in,
                              void* d_out, int out_size)
{
    const float* im1 = (const float*)d_in[0];
    const float* im2 = (const float*)d_in[1];
    const float* C   = (const float*)d_in[2];
    const float* M1  = (const float*)d_in[3];
    const float* M2  = (const float*)d_in[4];
    float* out = (float*)d_out;

    dim3 grid(IMD / 16, IMD / 32, 64);  // (14, 7, 64) -> 6272 CTAs
    vm_kernel<<<grid, 256>>>(im1, im2, C, M1, M2, out);
}